// round 4
// baseline (speedup 1.0000x reference)
#include <cuda_runtime.h>
#include <cstdint>

// Problem constants
#define K_NODES 100000
#define K_RELS  500
#define K_MEM   512
#define K_IN    1024
#define K_BATCH 65536

// GEMM tiling
#define BM 128
#define BN 128
#define BK 32
#define STR 36                  // BK + 4 pad (16B-aligned, conflict-free frag loads)
#define TILE (BM * STR)         // floats per tile buffer (4608)
#define NIT (K_IN / BK)         // 32 k-iterations

__device__ __forceinline__ int decode_time(const void* p) {
    int i = *(const int*)p;
    if (i < 0 || i > 1000000) i = (int)__int_as_float(i);
    return i;
}

// ---------------------------------------------------------------------------
// Kernel 1: out[concat(entity, rel)] = memory * (t/(t+1) if t>1 else 1)
// ---------------------------------------------------------------------------
__global__ void init_out_kernel(const float* __restrict__ ent,
                                const float* __restrict__ rel,
                                const void* __restrict__ tp,
                                float* __restrict__ out) {
    const int t = decode_time(tp);
    const float s = (t > 1) ? (float)t / (float)(t + 1) : 1.0f;
    const long nent = (long)K_NODES * K_MEM;           // 51,200,000 (mult of 4)
    const long ntot = nent + (long)K_RELS * K_MEM;     // 51,456,000
    long i = ((long)blockIdx.x * blockDim.x + threadIdx.x) * 4;
    const long stride = (long)gridDim.x * blockDim.x * 4;
    for (; i < ntot; i += stride) {
        const float4 v = (i < nent) ? *(const float4*)(ent + i)
                                    : *(const float4*)(rel + (i - nent));
        float4 o;
        o.x = v.x * s; o.y = v.y * s; o.z = v.z * s; o.w = v.w * s;
        *(float4*)(out + i) = o;
    }
}

// ---------------------------------------------------------------------------
// Kernel 2: C = X @ W^T (+bias), scaled by 1/(t+1), scatter-added into out
// tf32 mma.sync (raw fp32 bits -> HW truncates to tf32: no CVT instructions),
// cp.async double-buffered. grid = (MEM/BN, BATCH/BM, 2), col tiles fastest
// for L2 reuse of the A row-tile.
// ---------------------------------------------------------------------------
__device__ __forceinline__ void cp16(void* smem_dst, const void* gsrc) {
    uint32_t d = (uint32_t)__cvta_generic_to_shared(smem_dst);
    asm volatile("cp.async.cg.shared.global [%0], [%1], 16;" :: "r"(d), "l"(gsrc));
}

__global__ __launch_bounds__(256, 2) void gemm_scatter_kernel(
    const float* __restrict__ Xn, const float* __restrict__ Xr,
    const float* __restrict__ Wn, const float* __restrict__ Wr,
    const float* __restrict__ bn, const float* __restrict__ br,
    const int* __restrict__ idn, const int* __restrict__ idr,
    const void* __restrict__ tp, float* __restrict__ out)
{
    extern __shared__ float smem[];   // [2 buffers][A tile | B tile], 73,728 B

    const int z = blockIdx.z;
    const float* __restrict__ X    = z ? Xr  : Xn;
    const float* __restrict__ W    = z ? Wr  : Wn;
    const float* __restrict__ bias = z ? br  : bn;
    const int*   __restrict__ ids  = z ? idr : idn;
    const int obase = z ? K_NODES : 0;

    const int t = decode_time(tp);
    const float inv = 1.0f / (float)(t + 1);

    const int bm    = blockIdx.y * BM;    // batch (row) tile origin
    const int bnoff = blockIdx.x * BN;    // output-dim (col) tile origin — fastest
    const int tid  = threadIdx.x;
    const int wid  = tid >> 5, lane = tid & 31;
    const int wm = (wid & 1) * 64;        // warp m offset in CTA tile
    const int wn = (wid >> 1) * 32;       // warp n offset in CTA tile
    const int grp = lane >> 2, tig = lane & 3;

    auto load_tiles = [&](int buf, int k0) {
        float* As = smem + buf * (2 * TILE);
        float* Bs = As + TILE;
        #pragma unroll
        for (int i = 0; i < 4; i++) {
            int idx = tid + i * 256;
            int row = idx >> 3, c4 = (idx & 7) << 2;       // 8 float4 per 32-float row
            cp16(As + row * STR + c4, X + (long)(bm + row) * K_IN + k0 + c4);
        }
        #pragma unroll
        for (int i = 0; i < 4; i++) {
            int idx = tid + i * 256;
            int row = idx >> 3, c4 = (idx & 7) << 2;
            cp16(Bs + row * STR + c4, W + (long)(bnoff + row) * K_IN + k0 + c4);
        }
        asm volatile("cp.async.commit_group;");
    };

    float acc[4][4][4] = {};   // [m-tile][n-tile][frag], 64 accumulators

    load_tiles(0, 0);
    load_tiles(1, BK);

    for (int it = 0; it < NIT; ++it) {
        asm volatile("cp.async.wait_group 1;");
        __syncthreads();

        const float* As = smem + (it & 1) * (2 * TILE);
        const float* Bs = As + TILE;

        #pragma unroll
        for (int ks = 0; ks < 4; ++ks) {           // 4 k-steps of 8
            const int k0 = ks * 8;
            uint32_t af[4][4], bf[4][2];
            // Raw fp32 bit loads — tensor core reads only tf32 bits (truncation)
            #pragma unroll
            for (int mt = 0; mt < 4; ++mt) {
                const uint32_t* ap =
                    (const uint32_t*)(As + (wm + mt * 16 + grp) * STR + k0 + tig);
                af[mt][0] = ap[0];
                af[mt][1] = ap[8 * STR];
                af[mt][2] = ap[4];
                af[mt][3] = ap[8 * STR + 4];
            }
            #pragma unroll
            for (int nt = 0; nt < 4; ++nt) {
                const uint32_t* bp =
                    (const uint32_t*)(Bs + (wn + nt * 8 + grp) * STR + k0 + tig);
                bf[nt][0] = bp[0];
                bf[nt][1] = bp[4];
            }
            #pragma unroll
            for (int mt = 0; mt < 4; ++mt)
                #pragma unroll
                for (int nt = 0; nt < 4; ++nt)
                    asm volatile(
                        "mma.sync.aligned.m16n8k8.row.col.f32.tf32.tf32.f32 "
                        "{%0,%1,%2,%3}, {%4,%5,%6,%7}, {%8,%9}, {%0,%1,%2,%3};"
                        : "+f"(acc[mt][nt][0]), "+f"(acc[mt][nt][1]),
                          "+f"(acc[mt][nt][2]), "+f"(acc[mt][nt][3])
                        : "r"(af[mt][0]), "r"(af[mt][1]), "r"(af[mt][2]), "r"(af[mt][3]),
                          "r"(bf[nt][0]), "r"(bf[nt][1]));
        }

        __syncthreads();
        if (it + 2 < NIT) load_tiles(it & 1, (it + 2) * BK);
        else asm volatile("cp.async.commit_group;");   // keep group count consistent
    }

    // Epilogue: (acc + bias) * inv, scatter-add via float2 vector atomics
    float2 bv[4];
    #pragma unroll
    for (int nt = 0; nt < 4; ++nt) {
        int col = bnoff + wn + nt * 8 + tig * 2;
        bv[nt].x = bias[col];
        bv[nt].y = bias[col + 1];
    }
    #pragma unroll
    for (int mt = 0; mt < 4; ++mt) {
        #pragma unroll
        for (int h = 0; h < 2; ++h) {
            const int gb = bm + wm + mt * 16 + grp + h * 8;    // global batch row
            const long orow = (long)(ids[gb] + obase);
            float* dst = out + orow * K_MEM;
            #pragma unroll
            for (int nt = 0; nt < 4; ++nt) {
                const int col = bnoff + wn + nt * 8 + tig * 2;
                float2 v;
                v.x = (acc[mt][nt][h * 2 + 0] + bv[nt].x) * inv;
                v.y = (acc[mt][nt][h * 2 + 1] + bv[nt].y) * inv;
                atomicAdd((float2*)(dst + col), v);            // red.global.add.v2.f32
            }
        }
    }
}

// ---------------------------------------------------------------------------
extern "C" void kernel_launch(void* const* d_in, const int* in_sizes, int n_in,
                              void* d_out, int out_size) {
    const float* Xn  = (const float*)d_in[0];   // nodes_embeddings [65536,1024]
    const float* Xr  = (const float*)d_in[1];   // rels_embeddings  [65536,1024]
    const int*   idn = (const int*)  d_in[2];   // nodes_ids [65536]
    const int*   idr = (const int*)  d_in[3];   // rels_ids  [65536]
    const float* ent = (const float*)d_in[4];   // entity_memory [100000,512]
    const float* rel = (const float*)d_in[5];   // rel_memory    [500,512]
    const float* Wn  = (const float*)d_in[6];   // W_node [512,1024]
    const float* bn  = (const float*)d_in[7];   // b_node [512]
    const float* Wr  = (const float*)d_in[8];   // W_rel  [512,1024]
    const float* br  = (const float*)d_in[9];   // b_rel  [512]
    const void*  tp  = d_in[10];                // time (scalar)
    float* out = (float*)d_out;                 // [100500, 512]

    // 1) out = scaled memory state
    init_out_kernel<<<1184, 256>>>(ent, rel, tp, out);

    // 2) GEMM + scatter-add (both matrices, z dim). Column tiles fastest.
    cudaFuncSetAttribute(gemm_scatter_kernel,
                         cudaFuncAttributeMaxDynamicSharedMemorySize,
                         4 * TILE * (int)sizeof(float));
    dim3 grid(K_MEM / BN, K_BATCH / BM, 2);
    gemm_scatter_kernel<<<grid, 256, 4 * TILE * sizeof(float)>>>(
        Xn, Xr, Wn, Wr, bn, br, idn, idr, tp, out);
}

// round 5
// speedup vs baseline: 1.4725x; 1.4725x over previous
#include <cuda_runtime.h>
#include <cstdint>

// Problem constants
#define K_NODES 100000
#define K_RELS  500
#define K_MEM   512
#define K_IN    1024
#define K_BATCH 65536

// GEMM tiling
#define BM 128
#define BN 128
#define BK 32
#define STR 40                  // BK + 8 pad: float2 frag loads conflict-free
#define TILE (BM * STR)         // floats per tile buffer (5120)
#define NIT (K_IN / BK)         // 32 k-iterations

__device__ __forceinline__ int decode_time(const void* p) {
    int i = *(const int*)p;
    if (i < 0 || i > 1000000) i = (int)__int_as_float(i);
    return i;
}

// ---------------------------------------------------------------------------
// Kernel 1: out[concat(entity, rel)] = memory * (t/(t+1) if t>1 else 1)
// ---------------------------------------------------------------------------
__global__ void init_out_kernel(const float* __restrict__ ent,
                                const float* __restrict__ rel,
                                const void* __restrict__ tp,
                                float* __restrict__ out) {
    const int t = decode_time(tp);
    const float s = (t > 1) ? (float)t / (float)(t + 1) : 1.0f;
    const long nent = (long)K_NODES * K_MEM;
    const long ntot = nent + (long)K_RELS * K_MEM;
    long i = ((long)blockIdx.x * blockDim.x + threadIdx.x) * 4;
    const long stride = (long)gridDim.x * blockDim.x * 4;
    for (; i < ntot; i += stride) {
        const float4 v = (i < nent) ? *(const float4*)(ent + i)
                                    : *(const float4*)(rel + (i - nent));
        float4 o;
        o.x = v.x * s; o.y = v.y * s; o.z = v.z * s; o.w = v.w * s;
        *(float4*)(out + i) = o;
    }
}

// ---------------------------------------------------------------------------
// Kernel 2: C = X @ W^T (+bias), scaled by 1/(t+1), scatter-added into out
// tf32 mma.sync + cvt.rna, cp.async double-buffered.
// Fragment loads are LDS.64: thread tig reads float2 at k0+2*tig and labels
// (.x -> logical k=tig, .y -> logical k=tig+4) consistently for A and B —
// dot products are k-permutation invariant, so no storage permutation needed.
// grid = (MEM/BN, BATCH/BM, 2), col tiles fastest for L2 reuse of A.
// ---------------------------------------------------------------------------
__device__ __forceinline__ uint32_t f2tf(float f) {
    uint32_t u;
    asm("cvt.rna.tf32.f32 %0, %1;" : "=r"(u) : "f"(f));
    return u;
}

__device__ __forceinline__ void cp16(void* smem_dst, const void* gsrc) {
    uint32_t d = (uint32_t)__cvta_generic_to_shared(smem_dst);
    asm volatile("cp.async.cg.shared.global [%0], [%1], 16;" :: "r"(d), "l"(gsrc));
}

__global__ __launch_bounds__(256, 2) void gemm_scatter_kernel(
    const float* __restrict__ Xn, const float* __restrict__ Xr,
    const float* __restrict__ Wn, const float* __restrict__ Wr,
    const float* __restrict__ bn, const float* __restrict__ br,
    const int* __restrict__ idn, const int* __restrict__ idr,
    const void* __restrict__ tp, float* __restrict__ out)
{
    extern __shared__ float smem[];   // [2 buffers][A tile | B tile], 81,920 B

    const int z = blockIdx.z;
    const float* __restrict__ X    = z ? Xr  : Xn;
    const float* __restrict__ W    = z ? Wr  : Wn;
    const float* __restrict__ bias = z ? br  : bn;
    const int*   __restrict__ ids  = z ? idr : idn;
    const int obase = z ? K_NODES : 0;

    const int t = decode_time(tp);
    const float inv = 1.0f / (float)(t + 1);

    const int bm    = blockIdx.y * BM;    // batch (row) tile origin
    const int bnoff = blockIdx.x * BN;    // output-dim (col) tile origin — fastest
    const int tid  = threadIdx.x;
    const int wid  = tid >> 5, lane = tid & 31;
    const int wm = (wid & 1) * 64;        // warp m offset in CTA tile
    const int wn = (wid >> 1) * 32;       // warp n offset in CTA tile
    const int grp = lane >> 2, tig = lane & 3;

    auto load_tiles = [&](int buf, int k0) {
        float* As = smem + buf * (2 * TILE);
        float* Bs = As + TILE;
        #pragma unroll
        for (int i = 0; i < 4; i++) {
            int idx = tid + i * 256;
            int row = idx >> 3, c4 = (idx & 7) << 2;       // 8 float4 per 32-float row
            cp16(As + row * STR + c4, X + (long)(bm + row) * K_IN + k0 + c4);
        }
        #pragma unroll
        for (int i = 0; i < 4; i++) {
            int idx = tid + i * 256;
            int row = idx >> 3, c4 = (idx & 7) << 2;
            cp16(Bs + row * STR + c4, W + (long)(bnoff + row) * K_IN + k0 + c4);
        }
        asm volatile("cp.async.commit_group;");
    };

    float acc[4][4][4] = {};   // [m-tile][n-tile][frag], 64 accumulators

    load_tiles(0, 0);
    load_tiles(1, BK);

    for (int it = 0; it < NIT; ++it) {
        asm volatile("cp.async.wait_group 1;");
        __syncthreads();

        const float* As = smem + (it & 1) * (2 * TILE);
        const float* Bs = As + TILE;

        #pragma unroll
        for (int ks = 0; ks < 4; ++ks) {           // 4 k-steps of 8
            const int k0 = ks * 8;
            uint32_t af[4][4], bf[4][2];
            #pragma unroll
            for (int mt = 0; mt < 4; ++mt) {
                const float* ap = As + (wm + mt * 16 + grp) * STR + k0 + 2 * tig;
                const float2 v0 = *(const float2*)(ap);
                const float2 v1 = *(const float2*)(ap + 8 * STR);
                af[mt][0] = f2tf(v0.x);   // logical k = tig
                af[mt][1] = f2tf(v1.x);
                af[mt][2] = f2tf(v0.y);   // logical k = tig+4
                af[mt][3] = f2tf(v1.y);
            }
            #pragma unroll
            for (int nt = 0; nt < 4; ++nt) {
                const float* bp = Bs + (wn + nt * 8 + grp) * STR + k0 + 2 * tig;
                const float2 v = *(const float2*)(bp);
                bf[nt][0] = f2tf(v.x);
                bf[nt][1] = f2tf(v.y);
            }
            #pragma unroll
            for (int mt = 0; mt < 4; ++mt)
                #pragma unroll
                for (int nt = 0; nt < 4; ++nt)
                    asm volatile(
                        "mma.sync.aligned.m16n8k8.row.col.f32.tf32.tf32.f32 "
                        "{%0,%1,%2,%3}, {%4,%5,%6,%7}, {%8,%9}, {%0,%1,%2,%3};"
                        : "+f"(acc[mt][nt][0]), "+f"(acc[mt][nt][1]),
                          "+f"(acc[mt][nt][2]), "+f"(acc[mt][nt][3])
                        : "r"(af[mt][0]), "r"(af[mt][1]), "r"(af[mt][2]), "r"(af[mt][3]),
                          "r"(bf[nt][0]), "r"(bf[nt][1]));
        }

        __syncthreads();
        if (it + 2 < NIT) load_tiles(it & 1, (it + 2) * BK);
        else asm volatile("cp.async.commit_group;");   // keep group count consistent
    }

    // Epilogue: (acc + bias) * inv, scatter-add via float2 vector atomics
    float2 bv[4];
    #pragma unroll
    for (int nt = 0; nt < 4; ++nt) {
        int col = bnoff + wn + nt * 8 + tig * 2;
        bv[nt].x = bias[col];
        bv[nt].y = bias[col + 1];
    }
    #pragma unroll
    for (int mt = 0; mt < 4; ++mt) {
        #pragma unroll
        for (int h = 0; h < 2; ++h) {
            const int gb = bm + wm + mt * 16 + grp + h * 8;    // global batch row
            const long orow = (long)(ids[gb] + obase);
            float* dst = out + orow * K_MEM;
            #pragma unroll
            for (int nt = 0; nt < 4; ++nt) {
                const int col = bnoff + wn + nt * 8 + tig * 2;
                float2 v;
                v.x = (acc[mt][nt][h * 2 + 0] + bv[nt].x) * inv;
                v.y = (acc[mt][nt][h * 2 + 1] + bv[nt].y) * inv;
                atomicAdd((float2*)(dst + col), v);            // red.global.add.v2.f32
            }
        }
    }
}

// ---------------------------------------------------------------------------
extern "C" void kernel_launch(void* const* d_in, const int* in_sizes, int n_in,
                              void* d_out, int out_size) {
    const float* Xn  = (const float*)d_in[0];   // nodes_embeddings [65536,1024]
    const float* Xr  = (const float*)d_in[1];   // rels_embeddings  [65536,1024]
    const int*   idn = (const int*)  d_in[2];   // nodes_ids [65536]
    const int*   idr = (const int*)  d_in[3];   // rels_ids  [65536]
    const float* ent = (const float*)d_in[4];   // entity_memory [100000,512]
    const float* rel = (const float*)d_in[5];   // rel_memory    [500,512]
    const float* Wn  = (const float*)d_in[6];   // W_node [512,1024]
    const float* bn  = (const float*)d_in[7];   // b_node [512]
    const float* Wr  = (const float*)d_in[8];   // W_rel  [512,1024]
    const float* br  = (const float*)d_in[9];   // b_rel  [512]
    const void*  tp  = d_in[10];                // time (scalar)
    float* out = (float*)d_out;                 // [100500, 512]

    // 1) out = scaled memory state
    init_out_kernel<<<1184, 256>>>(ent, rel, tp, out);

    // 2) GEMM + scatter-add (both matrices, z dim). Column tiles fastest.
    cudaFuncSetAttribute(gemm_scatter_kernel,
                         cudaFuncAttributeMaxDynamicSharedMemorySize,
                         4 * TILE * (int)sizeof(float));
    dim3 grid(K_MEM / BN, K_BATCH / BM, 2);
    gemm_scatter_kernel<<<grid, 256, 4 * TILE * sizeof(float)>>>(
        Xn, Xr, Wn, Wr, bn, br, idn, idr, tp, out);
}

// round 6
// speedup vs baseline: 1.5537x; 1.0551x over previous
#include <cuda_runtime.h>
#include <cstdint>

// Problem constants
#define K_NODES 100000
#define K_RELS  500
#define K_MEM   512
#define K_IN    1024
#define K_BATCH 65536

// GEMM tiling
#define BM 128
#define BN 128
#define BK 32
#define STR 36                  // floats/row: 144B -> ldmatrix phases conflict-free
#define TILE (BM * STR)         // 4608 floats per tile
#define BUF_BYTES (2 * TILE * 4)
#define NIT (K_IN / BK)         // 32 k-iterations

__device__ __forceinline__ int decode_time(const void* p) {
    int i = *(const int*)p;
    if (i < 0 || i > 1000000) i = (int)__int_as_float(i);
    return i;
}

// ---------------------------------------------------------------------------
// Kernel 1: out[concat(entity, rel)] = memory * (t/(t+1) if t>1 else 1)
// ---------------------------------------------------------------------------
__global__ void init_out_kernel(const float* __restrict__ ent,
                                const float* __restrict__ rel,
                                const void* __restrict__ tp,
                                float* __restrict__ out) {
    const int t = decode_time(tp);
    const float s = (t > 1) ? (float)t / (float)(t + 1) : 1.0f;
    const long nent = (long)K_NODES * K_MEM;
    const long ntot = nent + (long)K_RELS * K_MEM;
    long i = ((long)blockIdx.x * blockDim.x + threadIdx.x) * 4;
    const long stride = (long)gridDim.x * blockDim.x * 4;
    for (; i < ntot; i += stride) {
        const float4 v = (i < nent) ? *(const float4*)(ent + i)
                                    : *(const float4*)(rel + (i - nent));
        float4 o;
        o.x = v.x * s; o.y = v.y * s; o.z = v.z * s; o.w = v.w * s;
        *(float4*)(out + i) = o;
    }
}

// ---------------------------------------------------------------------------
// Kernel 2: C = X @ W^T (+bias), scaled by 1/(t+1), scatter-added into out.
// tf32 mma.sync + cvt.rna; fragments via ldmatrix.m8n8.x4.b16 (exact tf32
// fragment distribution); cp.async double-buffered with incremental pointers.
// grid = (MEM/BN, BATCH/BM, 2), col tiles fastest for L2 reuse of A.
// ---------------------------------------------------------------------------
__device__ __forceinline__ uint32_t f2tf(float f) {
    uint32_t u;
    asm("cvt.rna.tf32.f32 %0, %1;" : "=r"(u) : "f"(f));
    return u;
}
__device__ __forceinline__ void cp16(void* smem_dst, const void* gsrc) {
    uint32_t d = (uint32_t)__cvta_generic_to_shared(smem_dst);
    asm volatile("cp.async.cg.shared.global [%0], [%1], 16;" :: "r"(d), "l"(gsrc));
}
__device__ __forceinline__ void ldsm4(uint32_t& r0, uint32_t& r1,
                                      uint32_t& r2, uint32_t& r3, uint32_t a) {
    asm volatile("ldmatrix.sync.aligned.m8n8.x4.shared.b16 {%0,%1,%2,%3}, [%4];"
                 : "=r"(r0), "=r"(r1), "=r"(r2), "=r"(r3) : "r"(a));
}

__global__ __launch_bounds__(256, 2) void gemm_scatter_kernel(
    const float* __restrict__ Xn, const float* __restrict__ Xr,
    const float* __restrict__ Wn, const float* __restrict__ Wr,
    const float* __restrict__ bn, const float* __restrict__ br,
    const int* __restrict__ idn, const int* __restrict__ idr,
    const void* __restrict__ tp, float* __restrict__ out)
{
    extern __shared__ float smem[];   // [2 buffers][A | B], 73,728 B

    const int z = blockIdx.z;
    const float* __restrict__ X    = z ? Xr  : Xn;
    const float* __restrict__ W    = z ? Wr  : Wn;
    const float* __restrict__ bias = z ? br  : bn;
    const int*   __restrict__ ids  = z ? idr : idn;
    const int obase = z ? K_NODES : 0;

    const int t = decode_time(tp);
    const float inv = 1.0f / (float)(t + 1);

    const int bm    = blockIdx.y * BM;
    const int bnoff = blockIdx.x * BN;
    const int tid  = threadIdx.x;
    const int wid  = tid >> 5, lane = tid & 31;
    const int wm = (wid & 1) * 64;
    const int wn = (wid >> 1) * 32;
    const int grp = lane >> 2, tig = lane & 3;

    // ldmatrix per-lane offsets (bytes).
    // A x4 tiles: [rows+0..7,k0] [rows+8..15,k0] [rows,k0+4] [rows+8,k0+4]
    const uint32_t aoff =
        ((((lane & 7) + ((lane >> 3) & 1) * 8) * STR) + ((lane >> 4) & 1) * 4) * 4;
    // B x4 tiles: [nt rows,k0] [nt rows,k0+4] [nt+1 rows,k0] [nt+1 rows,k0+4]
    const uint32_t boff =
        ((((lane & 7) + ((lane >> 4) & 1) * 8) * STR) + ((lane >> 3) & 1) * 4) * 4;

    const uint32_t smem0 = (uint32_t)__cvta_generic_to_shared(smem);
    const uint32_t aBase0 = smem0 + (uint32_t)(wm * STR * 4) + aoff;
    const uint32_t bBase0 = smem0 + (uint32_t)(TILE * 4) + (uint32_t)(wn * STR * 4) + boff;

    // Incremental fill pointers: thread covers row tid>>3 (+i*32), 16B chunk tid&7
    const char* gA = (const char*)(X + (size_t)(bm    + (tid >> 3)) * K_IN + ((tid & 7) << 2));
    const char* gB = (const char*)(W + (size_t)(bnoff + (tid >> 3)) * K_IN + ((tid & 7) << 2));
    const int sdst = (tid >> 3) * STR + ((tid & 7) << 2);

    auto fill = [&](int buf) {
        float* dA = smem + buf * (2 * TILE) + sdst;
        float* dB = dA + TILE;
        #pragma unroll
        for (int i = 0; i < 4; i++)
            cp16(dA + i * 32 * STR, gA + (size_t)i * 32 * K_IN * 4);
        #pragma unroll
        for (int i = 0; i < 4; i++)
            cp16(dB + i * 32 * STR, gB + (size_t)i * 32 * K_IN * 4);
        asm volatile("cp.async.commit_group;");
        gA += BK * 4;
        gB += BK * 4;
    };

    float acc[4][4][4] = {};   // 64 accumulators

    fill(0); fill(1);

    for (int it = 0; it < NIT; ++it) {
        asm volatile("cp.async.wait_group 1;");
        __syncthreads();

        const uint32_t aB = aBase0 + (it & 1) * BUF_BYTES;
        const uint32_t bB = bBase0 + (it & 1) * BUF_BYTES;

        #pragma unroll
        for (int ks = 0; ks < 4; ++ks) {
            uint32_t af[4][4], bf[4][2];
            #pragma unroll
            for (int mt = 0; mt < 4; ++mt) {
                uint32_t r0, r1, r2, r3;
                ldsm4(r0, r1, r2, r3, aB + mt * (16 * STR * 4) + ks * 32);
                af[mt][0] = f2tf(__uint_as_float(r0));
                af[mt][1] = f2tf(__uint_as_float(r1));
                af[mt][2] = f2tf(__uint_as_float(r2));
                af[mt][3] = f2tf(__uint_as_float(r3));
            }
            #pragma unroll
            for (int np = 0; np < 2; ++np) {
                uint32_t r0, r1, r2, r3;
                ldsm4(r0, r1, r2, r3, bB + np * (16 * STR * 4) + ks * 32);
                bf[2 * np][0]     = f2tf(__uint_as_float(r0));
                bf[2 * np][1]     = f2tf(__uint_as_float(r1));
                bf[2 * np + 1][0] = f2tf(__uint_as_float(r2));
                bf[2 * np + 1][1] = f2tf(__uint_as_float(r3));
            }
            #pragma unroll
            for (int mt = 0; mt < 4; ++mt)
                #pragma unroll
                for (int nt = 0; nt < 4; ++nt)
                    asm volatile(
                        "mma.sync.aligned.m16n8k8.row.col.f32.tf32.tf32.f32 "
                        "{%0,%1,%2,%3}, {%4,%5,%6,%7}, {%8,%9}, {%0,%1,%2,%3};"
                        : "+f"(acc[mt][nt][0]), "+f"(acc[mt][nt][1]),
                          "+f"(acc[mt][nt][2]), "+f"(acc[mt][nt][3])
                        : "r"(af[mt][0]), "r"(af[mt][1]), "r"(af[mt][2]), "r"(af[mt][3]),
                          "r"(bf[nt][0]), "r"(bf[nt][1]));
        }

        __syncthreads();
        if (it + 2 < NIT) fill(it & 1);
        else asm volatile("cp.async.commit_group;");   // keep group count stable
    }

    // Epilogue: (acc + bias) * inv, scatter-add via float2 vector atomics
    float2 bv[4];
    #pragma unroll
    for (int nt = 0; nt < 4; ++nt) {
        int col = bnoff + wn + nt * 8 + tig * 2;
        bv[nt].x = bias[col];
        bv[nt].y = bias[col + 1];
    }
    #pragma unroll
    for (int mt = 0; mt < 4; ++mt) {
        #pragma unroll
        for (int h = 0; h < 2; ++h) {
            const int gb = bm + wm + mt * 16 + grp + h * 8;
            const long orow = (long)(ids[gb] + obase);
            float* dst = out + orow * K_MEM;
            #pragma unroll
            for (int nt = 0; nt < 4; ++nt) {
                const int col = bnoff + wn + nt * 8 + tig * 2;
                float2 v;
                v.x = (acc[mt][nt][h * 2 + 0] + bv[nt].x) * inv;
                v.y = (acc[mt][nt][h * 2 + 1] + bv[nt].y) * inv;
                atomicAdd((float2*)(dst + col), v);
            }
        }
    }
}

// ---------------------------------------------------------------------------
extern "C" void kernel_launch(void* const* d_in, const int* in_sizes, int n_in,
                              void* d_out, int out_size) {
    const float* Xn  = (const float*)d_in[0];
    const float* Xr  = (const float*)d_in[1];
    const int*   idn = (const int*)  d_in[2];
    const int*   idr = (const int*)  d_in[3];
    const float* ent = (const float*)d_in[4];
    const float* rel = (const float*)d_in[5];
    const float* Wn  = (const float*)d_in[6];
    const float* bn  = (const float*)d_in[7];
    const float* Wr  = (const float*)d_in[8];
    const float* br  = (const float*)d_in[9];
    const void*  tp  = d_in[10];
    float* out = (float*)d_out;

    init_out_kernel<<<1184, 256>>>(ent, rel, tp, out);

    cudaFuncSetAttribute(gemm_scatter_kernel,
                         cudaFuncAttributeMaxDynamicSharedMemorySize,
                         4 * TILE * (int)sizeof(float));
    dim3 grid(K_MEM / BN, K_BATCH / BM, 2);
    gemm_scatter_kernel<<<grid, 256, 4 * TILE * sizeof(float)>>>(
        Xn, Xr, Wn, Wr, bn, br, idn, idr, tp, out);
}